// round 1
// baseline (speedup 1.0000x reference)
#include <cuda_runtime.h>
#include <math.h>

#define NB 32
#define HW 1024

#define CKC 169   // x_ul_b channels
#define CQC 166   // ul_b channels
#define COC 160   // ul channels
#define KDIM 16
#define VDIM 80

// ---------------- scratch (static device memory; no allocations) ----------------
__device__ float g_cat [(size_t)NB * CKC * HW];   // x_ul_b  [n,169,1024]; ul_b = view +3*HW
__device__ float g_h   [(size_t)NB * CKC * HW];   // GRN hidden (largest C=169)
__device__ float g_gout[(size_t)NB * CKC * HW];   // GRN output (reused per branch)
__device__ float g_keys[(size_t)NB * KDIM * HW];
__device__ float g_quer[(size_t)NB * KDIM * HW];
__device__ float g_vals[(size_t)NB * VDIM * HW];
__device__ float g_att [(size_t)NB * HW * HW];    // presoftmax -> att weights (in place)
__device__ float g_attv[(size_t)NB * VDIM * HW];

__device__ __forceinline__ float eluf(float v) { return v > 0.f ? v : (expf(v) - 1.f); }

// ---------------- concat inputs into [n,169,hw] ----------------
__global__ void build_cat_kernel(const float* __restrict__ x, const float* __restrict__ ul,
                                 const float* __restrict__ b, float* __restrict__ cat) {
    long idx = (long)blockIdx.x * blockDim.x + threadIdx.x;
    const long total = (long)NB * CKC * HW;
    if (idx >= total) return;
    int p = (int)(idx % HW);
    int c = (int)((idx / HW) % CKC);
    int n = (int)(idx / ((long)CKC * HW));
    float v;
    if (c < 3)        v = x [((long)n * 3   + c        ) * HW + p];
    else if (c < 163) v = ul[((long)n * 160 + (c - 3)  ) * HW + p];
    else              v = b [((long)n * 6   + (c - 163)) * HW + p];
    cat[idx] = v;
}

// ---------------- H = W * concat_elu(X) + bias   (optionally accumulate) ----------------
// X: [NB, Cin, HW] with batch stride xStride.  W: [Cout, 2*Cin] row-major.
// Tile: 64 out-ch x 64 px, K-chunks of 16 input channels (=32 features).
__global__ void gemm_celu_kernel(const float* __restrict__ X, long xStride, int Cin,
                                 const float* __restrict__ W, const float* __restrict__ bias, int Cout,
                                 float* __restrict__ Out, long oStride, int accumulate) {
    __shared__ float sW[32][64];
    __shared__ float sX[32][64];
    const int n  = blockIdx.y >> 4;
    const int p0 = (blockIdx.y & 15) * 64;
    const int o0 = blockIdx.x * 64;
    const float* Xn = X + (long)n * xStride;
    const int tx = threadIdx.x & 15, ty = threadIdx.x >> 4;
    const int fw   = threadIdx.x & 31;   // feature index for W tile load
    const int orow = threadIdx.x >> 5;   // 0..7
    const int pxl  = threadIdx.x & 63;
    const int crow = threadIdx.x >> 6;   // 0..3
    float acc[4][4] = {};

    for (int c0 = 0; c0 < Cin; c0 += 16) {
        const int  cbase = c0 + (fw & 15);
        const int  wcol  = (fw < 16) ? cbase : (Cin + cbase);
        const bool cok   = cbase < Cin;
        #pragma unroll
        for (int pass = 0; pass < 8; ++pass) {
            const int o = o0 + orow + pass * 8;
            sW[fw][orow + pass * 8] = (cok && o < Cout) ? W[(long)o * (2 * Cin) + wcol] : 0.f;
        }
        #pragma unroll
        for (int pass = 0; pass < 4; ++pass) {
            const int cc = crow + pass * 4;
            const int c  = c0 + cc;
            const float v = (c < Cin) ? Xn[(long)c * HW + p0 + pxl] : 0.f;
            sX[cc][pxl]      = eluf(v);
            sX[cc + 16][pxl] = eluf(-v);
        }
        __syncthreads();
        #pragma unroll
        for (int f = 0; f < 32; ++f) {
            const float4 w4 = *reinterpret_cast<const float4*>(&sW[f][ty * 4]);
            const float4 x4 = *reinterpret_cast<const float4*>(&sX[f][tx * 4]);
            const float wr[4] = {w4.x, w4.y, w4.z, w4.w};
            const float xr[4] = {x4.x, x4.y, x4.z, x4.w};
            #pragma unroll
            for (int i = 0; i < 4; ++i)
                #pragma unroll
                for (int j = 0; j < 4; ++j)
                    acc[i][j] = fmaf(wr[i], xr[j], acc[i][j]);
        }
        __syncthreads();
    }

    #pragma unroll
    for (int i = 0; i < 4; ++i) {
        const int o = o0 + ty * 4 + i;
        if (o >= Cout) continue;
        float* dst = Out + (long)n * oStride + (long)o * HW + p0 + tx * 4;
        const float bo_ = bias[o];
        float4 r;
        r.x = acc[i][0] + bo_; r.y = acc[i][1] + bo_;
        r.z = acc[i][2] + bo_; r.w = acc[i][3] + bo_;
        if (accumulate) {
            const float4 prev = *reinterpret_cast<const float4*>(dst);
            r.x += prev.x; r.y += prev.y; r.z += prev.z; r.w += prev.w;
        }
        *reinterpret_cast<float4*>(dst) = r;
    }
}

// ---------------- GRN tail: out = Xres + ga*sigmoid(gb), [ga;gb] = Wo*concat_elu(H)+bo ----------------
__global__ void grn_final_kernel(const float* __restrict__ H, long hStride, int C,
                                 const float* __restrict__ Wo, const float* __restrict__ bo,
                                 const float* __restrict__ Xres, long xStride,
                                 float* __restrict__ Out, long oStride) {
    __shared__ float sWa[32][64];
    __shared__ float sWb[32][64];
    __shared__ float sX [32][64];
    const int n  = blockIdx.y >> 4;
    const int p0 = (blockIdx.y & 15) * 64;
    const int o0 = blockIdx.x * 64;
    const float* Hn = H + (long)n * hStride;
    const int tx = threadIdx.x & 15, ty = threadIdx.x >> 4;
    const int fw   = threadIdx.x & 31;
    const int orow = threadIdx.x >> 5;
    const int pxl  = threadIdx.x & 63;
    const int crow = threadIdx.x >> 6;
    float acca[4][4] = {};
    float accb[4][4] = {};

    for (int c0 = 0; c0 < C; c0 += 16) {
        const int  cbase = c0 + (fw & 15);
        const int  wcol  = (fw < 16) ? cbase : (C + cbase);
        const bool cok   = cbase < C;
        #pragma unroll
        for (int pass = 0; pass < 8; ++pass) {
            const int o = o0 + orow + pass * 8;
            float wa = 0.f, wb = 0.f;
            if (cok && o < C) {
                wa = Wo[(long)o       * (2 * C) + wcol];
                wb = Wo[(long)(o + C) * (2 * C) + wcol];
            }
            sWa[fw][orow + pass * 8] = wa;
            sWb[fw][orow + pass * 8] = wb;
        }
        #pragma unroll
        for (int pass = 0; pass < 4; ++pass) {
            const int cc = crow + pass * 4;
            const int c  = c0 + cc;
            const float v = (c < C) ? Hn[(long)c * HW + p0 + pxl] : 0.f;
            sX[cc][pxl]      = eluf(v);
            sX[cc + 16][pxl] = eluf(-v);
        }
        __syncthreads();
        #pragma unroll
        for (int f = 0; f < 32; ++f) {
            const float4 wa4 = *reinterpret_cast<const float4*>(&sWa[f][ty * 4]);
            const float4 wb4 = *reinterpret_cast<const float4*>(&sWb[f][ty * 4]);
            const float4 x4  = *reinterpret_cast<const float4*>(&sX [f][tx * 4]);
            const float war[4] = {wa4.x, wa4.y, wa4.z, wa4.w};
            const float wbr[4] = {wb4.x, wb4.y, wb4.z, wb4.w};
            const float xr [4] = {x4.x,  x4.y,  x4.z,  x4.w};
            #pragma unroll
            for (int i = 0; i < 4; ++i)
                #pragma unroll
                for (int j = 0; j < 4; ++j) {
                    acca[i][j] = fmaf(war[i], xr[j], acca[i][j]);
                    accb[i][j] = fmaf(wbr[i], xr[j], accb[i][j]);
                }
        }
        __syncthreads();
    }

    #pragma unroll
    for (int i = 0; i < 4; ++i) {
        const int o = o0 + ty * 4 + i;
        if (o >= C) continue;
        const float ba = bo[o];
        const float bb = bo[o + C];
        const float4 xr4 = *reinterpret_cast<const float4*>(
            &Xres[(long)n * xStride + (long)o * HW + p0 + tx * 4]);
        const float xres[4] = {xr4.x, xr4.y, xr4.z, xr4.w};
        float rv[4];
        #pragma unroll
        for (int j = 0; j < 4; ++j) {
            const float ga = acca[i][j] + ba;
            const float gb = accb[i][j] + bb;
            const float sig = 1.f / (1.f + expf(-gb));
            rv[j] = xres[j] + ga * sig;
        }
        float4 r = {rv[0], rv[1], rv[2], rv[3]};
        *reinterpret_cast<float4*>(&Out[(long)n * oStride + (long)o * HW + p0 + tx * 4]) = r;
    }
}

// ---------------- small projection: Out[n,M,hw] = W[M,Cin]*X + b ----------------
template <int M>
__global__ void proj_kernel(const float* __restrict__ X, int Cin,
                            const float* __restrict__ W, const float* __restrict__ bias,
                            float* __restrict__ Out) {
    __shared__ float sW[M * 32];
    const int n = blockIdx.y;
    const int p = blockIdx.x * 128 + threadIdx.x;
    const float* Xn = X + (long)n * Cin * HW;
    float acc[M];
    #pragma unroll
    for (int o = 0; o < M; ++o) acc[o] = 0.f;

    for (int c0 = 0; c0 < Cin; c0 += 32) {
        __syncthreads();
        for (int i = threadIdx.x; i < M * 32; i += 128) {
            const int o = i >> 5, cc = i & 31;
            const int c = c0 + cc;
            sW[i] = (c < Cin) ? W[(long)o * Cin + c] : 0.f;
        }
        __syncthreads();
        const int nc = min(32, Cin - c0);
        for (int cc = 0; cc < nc; ++cc) {
            const float v = Xn[(long)(c0 + cc) * HW + p];
            #pragma unroll
            for (int o = 0; o < M; ++o) acc[o] = fmaf(sW[o * 32 + cc], v, acc[o]);
        }
    }
    #pragma unroll
    for (int o = 0; o < M; ++o)
        Out[((long)n * M + o) * HW + p] = acc[o] + bias[o];
}

// ---------------- presoftmax: S[n,q,k] = sum_j K[n,j,k]*Q[n,j,q]  (lower tiles only) ----------------
__global__ void qk_kernel(const float* __restrict__ Kt, const float* __restrict__ Qt,
                          float* __restrict__ S) {
    const int n  = blockIdx.z;
    const int q0 = blockIdx.y * 64;
    const int k0 = blockIdx.x * 64;
    if (k0 > q0) return;  // tile entirely above causal boundary: never read
    __shared__ float sK[16][64];
    __shared__ float sQ[16][64];
    const float* Kn = Kt + (long)n * KDIM * HW;
    const float* Qn = Qt + (long)n * KDIM * HW;
    const int p  = threadIdx.x & 63;
    const int jr = threadIdx.x >> 6;
    #pragma unroll
    for (int pass = 0; pass < 4; ++pass) {
        const int j = jr + pass * 4;
        sK[j][p] = Kn[(long)j * HW + k0 + p];
        sQ[j][p] = Qn[(long)j * HW + q0 + p];
    }
    __syncthreads();
    const int tx = threadIdx.x & 15, ty = threadIdx.x >> 4;
    float acc[4][4] = {};
    #pragma unroll
    for (int j = 0; j < 16; ++j) {
        const float4 q4 = *reinterpret_cast<const float4*>(&sQ[j][ty * 4]);
        const float4 k4 = *reinterpret_cast<const float4*>(&sK[j][tx * 4]);
        const float qr[4] = {q4.x, q4.y, q4.z, q4.w};
        const float kr[4] = {k4.x, k4.y, k4.z, k4.w};
        #pragma unroll
        for (int i = 0; i < 4; ++i)
            #pragma unroll
            for (int jj = 0; jj < 4; ++jj)
                acc[i][jj] = fmaf(qr[i], kr[jj], acc[i][jj]);
    }
    float* Sn = S + (long)n * HW * HW;
    #pragma unroll
    for (int i = 0; i < 4; ++i) {
        float4 r = {acc[i][0], acc[i][1], acc[i][2], acc[i][3]};
        *reinterpret_cast<float4*>(&Sn[(long)(q0 + ty * 4 + i) * HW + k0 + tx * 4]) = r;
    }
}

// ---------------- causal softmax per row (faithful to reference semantics) ----------------
// masked entries are 0 (not -inf); softmax over full row; re-mask; renorm by (sum + 1e-7).
// => w_k = exp(s_k - m) / (S_kept + eps*D),  m = max(0, max_{k<q} s),
//    D = S_kept + (HW-q)*exp(-m)
__global__ void softmax_kernel(float* __restrict__ S) {
    const int q = blockIdx.x;
    const int n = blockIdx.y;
    float* row = S + ((long)n * HW + (long)q) * HW;
    const int tid = threadIdx.x;  // 256
    __shared__ float red[256];

    float vals[4];
    float lmax = 0.f;  // masked zeros participate in the max
    #pragma unroll
    for (int i = 0; i < 4; ++i) {
        const int k = tid + i * 256;
        const float s = (k < q) ? row[k] : 0.f;
        vals[i] = s;
        if (k < q) lmax = fmaxf(lmax, s);
    }
    red[tid] = lmax;
    __syncthreads();
    for (int s2 = 128; s2 > 0; s2 >>= 1) {
        if (tid < s2) red[tid] = fmaxf(red[tid], red[tid + s2]);
        __syncthreads();
    }
    const float m = red[0];
    __syncthreads();

    float e[4];
    float lsum = 0.f;
    #pragma unroll
    for (int i = 0; i < 4; ++i) {
        const int k = tid + i * 256;
        e[i] = (k < q) ? expf(vals[i] - m) : 0.f;
        lsum += e[i];
    }
    red[tid] = lsum;
    __syncthreads();
    for (int s2 = 128; s2 > 0; s2 >>= 1) {
        if (tid < s2) red[tid] += red[tid + s2];
        __syncthreads();
    }
    const float Skept = red[0];
    const float D = Skept + (float)(HW - q) * expf(-m);
    const float inv = 1.f / (Skept + 1e-7f * D);
    #pragma unroll
    for (int i = 0; i < 4; ++i) {
        const int k = tid + i * 256;
        row[k] = e[i] * inv;
    }
}

// ---------------- AV: Out[n,v,q] = sum_j Att[n,q,j] * V[n,v,j]  (K-loop causally truncated) ----------------
__global__ void av_kernel(const float* __restrict__ Att, const float* __restrict__ V,
                          float* __restrict__ Out) {
    __shared__ float sV[16][80];
    __shared__ float sW[16][64];
    const int n  = blockIdx.y;
    const int q0 = blockIdx.x * 64;
    const float* An = Att + (long)n * HW * HW;
    const float* Vn = V + (long)n * VDIM * HW;
    const int tx = threadIdx.x & 15, ty = threadIdx.x >> 4;
    float acc[5][4] = {};
    const int jmax = min(HW, q0 + 64);  // att[q,j]==0 for j>=q

    for (int j0 = 0; j0 < jmax; j0 += 16) {
        for (int i = threadIdx.x; i < 16 * 80; i += 256) {
            const int v = i >> 4, jj = i & 15;
            sV[jj][v] = Vn[(long)v * HW + j0 + jj];
        }
        for (int i = threadIdx.x; i < 16 * 64; i += 256) {
            const int qq = i >> 4, jj = i & 15;
            sW[jj][qq] = An[(long)(q0 + qq) * HW + j0 + jj];
        }
        __syncthreads();
        #pragma unroll
        for (int jj = 0; jj < 16; ++jj) {
            const float4 w4 = *reinterpret_cast<const float4*>(&sW[jj][tx * 4]);
            const float wv[4] = {w4.x, w4.y, w4.z, w4.w};
            #pragma unroll
            for (int i = 0; i < 5; ++i) {
                const float vv = sV[jj][ty * 5 + i];
                #pragma unroll
                for (int j = 0; j < 4; ++j)
                    acc[i][j] = fmaf(vv, wv[j], acc[i][j]);
            }
        }
        __syncthreads();
    }
    #pragma unroll
    for (int i = 0; i < 5; ++i) {
        float4 r = {acc[i][0], acc[i][1], acc[i][2], acc[i][3]};
        *reinterpret_cast<float4*>(&Out[((long)n * VDIM + ty * 5 + i) * HW + q0 + tx * 4]) = r;
    }
}

// ---------------- launcher ----------------
extern "C" void kernel_launch(void* const* d_in, const int* in_sizes, int n_in,
                              void* d_out, int out_size) {
    (void)in_sizes; (void)n_in; (void)out_size;
    const float* x    = (const float*)d_in[0];
    const float* ul   = (const float*)d_in[1];
    const float* b    = (const float*)d_in[2];
    const float* gkWi = (const float*)d_in[3];
    const float* gkbi = (const float*)d_in[4];
    const float* gkWo = (const float*)d_in[5];
    const float* gkbo = (const float*)d_in[6];
    const float* gqWi = (const float*)d_in[7];
    const float* gqbi = (const float*)d_in[8];
    const float* gqWo = (const float*)d_in[9];
    const float* gqbo = (const float*)d_in[10];
    const float* gvWi = (const float*)d_in[11];
    const float* gvbi = (const float*)d_in[12];
    const float* gvWo = (const float*)d_in[13];
    const float* gvbo = (const float*)d_in[14];
    const float* nkW  = (const float*)d_in[15];
    const float* nkb  = (const float*)d_in[16];
    const float* nqW  = (const float*)d_in[17];
    const float* nqb  = (const float*)d_in[18];
    const float* nvW  = (const float*)d_in[19];
    const float* nvb  = (const float*)d_in[20];
    const float* goWi = (const float*)d_in[21];
    const float* gobi = (const float*)d_in[22];
    const float* goWs = (const float*)d_in[23];
    const float* gobs = (const float*)d_in[24];
    const float* goWo = (const float*)d_in[25];
    const float* gobo = (const float*)d_in[26];
    float* out = (float*)d_out;

    float *p_cat, *p_h, *p_gout, *p_keys, *p_quer, *p_vals, *p_att, *p_attv;
    cudaGetSymbolAddress((void**)&p_cat,  g_cat);
    cudaGetSymbolAddress((void**)&p_h,    g_h);
    cudaGetSymbolAddress((void**)&p_gout, g_gout);
    cudaGetSymbolAddress((void**)&p_keys, g_keys);
    cudaGetSymbolAddress((void**)&p_quer, g_quer);
    cudaGetSymbolAddress((void**)&p_vals, g_vals);
    cudaGetSymbolAddress((void**)&p_att,  g_att);
    cudaGetSymbolAddress((void**)&p_attv, g_attv);

    const long sCat = (long)CKC * HW;
    const long sQ   = (long)CQC * HW;
    const long sO   = (long)COC * HW;
    const long sV   = (long)VDIM * HW;

    // concat(x, ul, b)
    {
        const long total = (long)NB * CKC * HW;
        build_cat_kernel<<<(unsigned)((total + 255) / 256), 256>>>(x, ul, b, p_cat);
    }

    dim3 gridK(3, NB * 16);   // ceil(169/64)=3
    dim3 gridO(3, NB * 16);   // ceil(160/64)=3

    // --- GRN-K -> keys ---
    gemm_celu_kernel<<<gridK, 256>>>(p_cat, sCat, CKC, gkWi, gkbi, CKC, p_h, sCat, 0);
    grn_final_kernel<<<gridK, 256>>>(p_h, sCat, CKC, gkWo, gkbo, p_cat, sCat, p_gout, sCat);
    proj_kernel<KDIM><<<dim3(8, NB), 128>>>(p_gout, CKC, nkW, nkb, p_keys);

    // --- GRN-Q -> queries (ul_b is a channel-offset view of cat) ---
    gemm_celu_kernel<<<gridK, 256>>>(p_cat + 3 * HW, sCat, CQC, gqWi, gqbi, CQC, p_h, sQ, 0);
    grn_final_kernel<<<gridK, 256>>>(p_h, sQ, CQC, gqWo, gqbo, p_cat + 3 * HW, sCat, p_gout, sQ);
    proj_kernel<KDIM><<<dim3(8, NB), 128>>>(p_gout, CQC, nqW, nqb, p_quer);

    // --- GRN-V -> values ---
    gemm_celu_kernel<<<gridK, 256>>>(p_cat, sCat, CKC, gvWi, gvbi, CKC, p_h, sCat, 0);
    grn_final_kernel<<<gridK, 256>>>(p_h, sCat, CKC, gvWo, gvbo, p_cat, sCat, p_gout, sCat);
    proj_kernel<VDIM><<<dim3(8, NB), 128>>>(p_gout, CKC, nvW, nvb, p_vals);

    // --- attention ---
    qk_kernel<<<dim3(16, 16, NB), 256>>>(p_keys, p_quer, p_att);
    softmax_kernel<<<dim3(HW, NB), 256>>>(p_att);
    av_kernel<<<dim3(16, NB), 256>>>(p_att, p_vals, p_attv);

    // --- GRN-O (aux = att_v) -> output ---
    gemm_celu_kernel<<<gridO, 256>>>(ul, sO, COC, goWi, gobi, COC, p_h, sO, 0);
    gemm_celu_kernel<<<gridO, 256>>>(p_attv, sV, VDIM, goWs, gobs, COC, p_h, sO, 1);
    grn_final_kernel<<<gridO, 256>>>(p_h, sO, COC, goWo, gobo, ul, sO, out, sO);
}

// round 2
// speedup vs baseline: 1.3307x; 1.3307x over previous
#include <cuda_runtime.h>
#include <math.h>

#define NB 32
#define HW 1024

#define CKC 169   // x_ul_b channels
#define CQC 166   // ul_b channels
#define COC 160   // ul channels
#define KDIM 16
#define VDIM 80

// ---------------- scratch (static device memory; no allocations) ----------------
__device__ float g_cat [(size_t)NB * CKC * HW];   // x_ul_b  [n,169,1024]; ul_b = view +3*HW
__device__ float g_h   [(size_t)NB * CKC * HW];   // GRN hidden (largest C=169)
__device__ float g_gout[(size_t)NB * CKC * HW];   // GRN output (reused per branch)
__device__ float g_keys[(size_t)NB * KDIM * HW];
__device__ float g_quer[(size_t)NB * KDIM * HW];
__device__ float g_vals[(size_t)NB * VDIM * HW];
__device__ float g_att [(size_t)NB * HW * HW];    // presoftmax -> att weights (in place)
__device__ float g_attv[(size_t)NB * VDIM * HW];

__device__ __forceinline__ float eluf(float v) { return v > 0.f ? v : (expf(v) - 1.f); }

// ---------------- concat inputs into [n,169,hw] ----------------
__global__ void build_cat_kernel(const float* __restrict__ x, const float* __restrict__ ul,
                                 const float* __restrict__ b, float* __restrict__ cat) {
    long idx = (long)blockIdx.x * blockDim.x + threadIdx.x;
    const long total = (long)NB * CKC * HW;
    if (idx >= total) return;
    int p = (int)(idx % HW);
    int c = (int)((idx / HW) % CKC);
    int n = (int)(idx / ((long)CKC * HW));
    float v;
    if (c < 3)        v = x [((long)n * 3   + c        ) * HW + p];
    else if (c < 163) v = ul[((long)n * 160 + (c - 3)  ) * HW + p];
    else              v = b [((long)n * 6   + (c - 163)) * HW + p];
    cat[idx] = v;
}

// ============ Big GEMM: Out = W*concat_elu(X) [+ W2*concat_elu(X2)] + bias(+bias2) ============
// Tile 64 out x 128 px, 256 threads, 8x4 microtile, K-chunks of 16 channels (=32 features),
// register-staged prefetch of the next chunk.

#define GEMM_LOAD_CHUNK(kk)                                                          \
    {                                                                                \
        const float* Xs; const float* Ws; int Ci; long xs; int c0;                   \
        if ((kk) < nk1) { Xs = X;  Ws = W;  Ci = Cin;  xs = xStride;  c0 = (kk) * 16; } \
        else            { Xs = X2; Ws = W2; Ci = Cin2; xs = x2Stride; c0 = ((kk) - nk1) * 16; } \
        const int  cbase = c0 + (fw & 15);                                           \
        const int  wcol  = (fw < 16) ? cbase : (Ci + cbase);                         \
        const bool cok   = cbase < Ci;                                               \
        _Pragma("unroll")                                                            \
        for (int i = 0; i < 8; ++i) {                                                \
            const int o = o0 + o8 + i * 8;                                           \
            wreg[i] = (cok && o < Cout) ? Ws[(long)o * (2 * Ci) + wcol] : 0.f;       \
        }                                                                            \
        const float* Xn = Xs + (long)n * xs;                                         \
        _Pragma("unroll")                                                            \
        for (int i = 0; i < 8; ++i) {                                                \
            const int c = c0 + c2 + i * 2;                                           \
            xreg[i] = (c < Ci) ? Xn[(long)c * HW + p0 + px] : 0.f;                   \
        }                                                                            \
    }

#define GEMM_STORE_CHUNK()                                                           \
    {                                                                                \
        _Pragma("unroll")                                                            \
        for (int i = 0; i < 8; ++i) sW[fw][o8 + i * 8] = wreg[i];                    \
        _Pragma("unroll")                                                            \
        for (int i = 0; i < 8; ++i) {                                                \
            const int   cl = c2 + i * 2;                                             \
            const float v  = xreg[i];                                                \
            sX[cl][px]      = eluf(v);                                               \
            sX[cl + 16][px] = eluf(-v);                                              \
        }                                                                            \
    }

__global__ void __launch_bounds__(256)
gemm_celu_kernel(const float* __restrict__ X, long xStride, int Cin,
                 const float* __restrict__ W,
                 const float* __restrict__ X2, long x2Stride, int Cin2,
                 const float* __restrict__ W2,
                 const float* __restrict__ bias, const float* __restrict__ bias2,
                 int Cout, float* __restrict__ Out, long oStride) {
    __shared__ float sW[32][68];
    __shared__ float sX[32][128];
    const int tid = threadIdx.x;
    const int n  = blockIdx.y >> 3;
    const int p0 = (blockIdx.y & 7) * 128;
    const int o0 = blockIdx.x * 64;

    const int fw  = tid & 31;    // W: feature
    const int o8  = tid >> 5;    // W: out sub
    const int px  = tid & 127;   // X: pixel
    const int c2  = tid >> 7;    // X: channel sub
    const int ox  = tid & 7;     // compute: out group (8 rows each)
    const int pxg = tid >> 3;    // compute: px group (4 px each)

    const int nk1 = (Cin + 15) >> 4;
    const int nk2 = W2 ? ((Cin2 + 15) >> 4) : 0;
    const int nk  = nk1 + nk2;

    float wreg[8], xreg[8];
    float acc[8][4] = {};

    GEMM_LOAD_CHUNK(0);
    GEMM_STORE_CHUNK();
    __syncthreads();

    for (int k = 0; k < nk; ++k) {
        if (k + 1 < nk) GEMM_LOAD_CHUNK(k + 1);
        #pragma unroll
        for (int f = 0; f < 32; ++f) {
            const float4 w0 = *reinterpret_cast<const float4*>(&sW[f][ox * 8]);
            const float4 w1 = *reinterpret_cast<const float4*>(&sW[f][ox * 8 + 4]);
            const float4 xv = *reinterpret_cast<const float4*>(&sX[f][pxg * 4]);
            const float wr[8] = {w0.x, w0.y, w0.z, w0.w, w1.x, w1.y, w1.z, w1.w};
            const float xr[4] = {xv.x, xv.y, xv.z, xv.w};
            #pragma unroll
            for (int i = 0; i < 8; ++i)
                #pragma unroll
                for (int j = 0; j < 4; ++j)
                    acc[i][j] = fmaf(wr[i], xr[j], acc[i][j]);
        }
        __syncthreads();
        if (k + 1 < nk) { GEMM_STORE_CHUNK(); __syncthreads(); }
    }

    #pragma unroll
    for (int i = 0; i < 8; ++i) {
        const int o = o0 + ox * 8 + i;
        if (o >= Cout) continue;
        float bo_ = bias[o] + (bias2 ? bias2[o] : 0.f);
        float4 r = {acc[i][0] + bo_, acc[i][1] + bo_, acc[i][2] + bo_, acc[i][3] + bo_};
        *reinterpret_cast<float4*>(&Out[(long)n * oStride + (long)o * HW + p0 + pxg * 4]) = r;
    }
}

// ============ GRN tail: out = Xres + ga*sigmoid(gb), [ga;gb] = Wo*concat_elu(H)+bo ============
#define GRNF_LOAD_CHUNK(kk)                                                          \
    {                                                                                \
        const int  c0    = (kk) * 16;                                                \
        const int  cbase = c0 + (fw & 15);                                           \
        const int  wcol  = (fw < 16) ? cbase : (C + cbase);                          \
        const bool cok   = cbase < C;                                                \
        _Pragma("unroll")                                                            \
        for (int i = 0; i < 8; ++i) {                                                \
            const int o = o0 + o8 + i * 8;                                           \
            const bool ok = cok && o < C;                                            \
            wrega[i] = ok ? Wo[(long)o       * (2 * C) + wcol] : 0.f;                \
            wregb[i] = ok ? Wo[(long)(o + C) * (2 * C) + wcol] : 0.f;                \
        }                                                                            \
        _Pragma("unroll")                                                            \
        for (int i = 0; i < 8; ++i) {                                                \
            const int c = c0 + c2 + i * 2;                                           \
            xreg[i] = (c < C) ? Hn[(long)c * HW + p0 + px] : 0.f;                    \
        }                                                                            \
    }

#define GRNF_STORE_CHUNK()                                                           \
    {                                                                                \
        _Pragma("unroll")                                                            \
        for (int i = 0; i < 8; ++i) { sWa[fw][o8 + i * 8] = wrega[i]; sWb[fw][o8 + i * 8] = wregb[i]; } \
        _Pragma("unroll")                                                            \
        for (int i = 0; i < 8; ++i) {                                                \
            const int   cl = c2 + i * 2;                                             \
            const float v  = xreg[i];                                                \
            sX[cl][px]      = eluf(v);                                               \
            sX[cl + 16][px] = eluf(-v);                                              \
        }                                                                            \
    }

__global__ void __launch_bounds__(256, 2)
grn_final_kernel(const float* __restrict__ H, long hStride, int C,
                 const float* __restrict__ Wo, const float* __restrict__ bo,
                 const float* __restrict__ Xres, long xStride,
                 float* __restrict__ Out, long oStride) {
    __shared__ float sWa[32][68];
    __shared__ float sWb[32][68];
    __shared__ float sX [32][128];
    const int tid = threadIdx.x;
    const int n  = blockIdx.y >> 3;
    const int p0 = (blockIdx.y & 7) * 128;
    const int o0 = blockIdx.x * 64;
    const float* Hn = H + (long)n * hStride;

    const int fw  = tid & 31;
    const int o8  = tid >> 5;
    const int px  = tid & 127;
    const int c2  = tid >> 7;
    const int ox  = tid & 7;
    const int pxg = tid >> 3;

    const int nk = (C + 15) >> 4;
    float wrega[8], wregb[8], xreg[8];
    float acca[8][4] = {};
    float accb[8][4] = {};

    GRNF_LOAD_CHUNK(0);
    GRNF_STORE_CHUNK();
    __syncthreads();

    for (int k = 0; k < nk; ++k) {
        if (k + 1 < nk) GRNF_LOAD_CHUNK(k + 1);
        #pragma unroll
        for (int f = 0; f < 32; ++f) {
            const float4 a0 = *reinterpret_cast<const float4*>(&sWa[f][ox * 8]);
            const float4 a1 = *reinterpret_cast<const float4*>(&sWa[f][ox * 8 + 4]);
            const float4 b0 = *reinterpret_cast<const float4*>(&sWb[f][ox * 8]);
            const float4 b1 = *reinterpret_cast<const float4*>(&sWb[f][ox * 8 + 4]);
            const float4 xv = *reinterpret_cast<const float4*>(&sX[f][pxg * 4]);
            const float ar[8] = {a0.x, a0.y, a0.z, a0.w, a1.x, a1.y, a1.z, a1.w};
            const float br[8] = {b0.x, b0.y, b0.z, b0.w, b1.x, b1.y, b1.z, b1.w};
            const float xr[4] = {xv.x, xv.y, xv.z, xv.w};
            #pragma unroll
            for (int i = 0; i < 8; ++i)
                #pragma unroll
                for (int j = 0; j < 4; ++j) {
                    acca[i][j] = fmaf(ar[i], xr[j], acca[i][j]);
                    accb[i][j] = fmaf(br[i], xr[j], accb[i][j]);
                }
        }
        __syncthreads();
        if (k + 1 < nk) { GRNF_STORE_CHUNK(); __syncthreads(); }
    }

    #pragma unroll
    for (int i = 0; i < 8; ++i) {
        const int o = o0 + ox * 8 + i;
        if (o >= C) continue;
        const float ba = bo[o];
        const float bb = bo[o + C];
        const float4 xr4 = *reinterpret_cast<const float4*>(
            &Xres[(long)n * xStride + (long)o * HW + p0 + pxg * 4]);
        const float xres[4] = {xr4.x, xr4.y, xr4.z, xr4.w};
        float rv[4];
        #pragma unroll
        for (int j = 0; j < 4; ++j) {
            const float ga = acca[i][j] + ba;
            const float gb = accb[i][j] + bb;
            const float sig = 1.f / (1.f + expf(-gb));
            rv[j] = xres[j] + ga * sig;
        }
        float4 r = {rv[0], rv[1], rv[2], rv[3]};
        *reinterpret_cast<float4*>(&Out[(long)n * oStride + (long)o * HW + p0 + pxg * 4]) = r;
    }
}

// ---------------- small projection: Out[n, m0..m0+MT, hw] = W*X + b ----------------
template <int MT>
__global__ void __launch_bounds__(256)
proj_kernel(const float* __restrict__ X, int Cin,
            const float* __restrict__ W, const float* __restrict__ bias,
            float* __restrict__ Out, int M) {
    __shared__ float sW[MT * 176];
    const int n  = blockIdx.y;
    const int m0 = blockIdx.z * MT;
    const int p  = blockIdx.x * 256 + threadIdx.x;
    for (int i = threadIdx.x; i < MT * Cin; i += 256) {
        const int o = i / Cin, c = i - o * Cin;
        sW[o * 176 + c] = W[(long)(m0 + o) * Cin + c];
    }
    __syncthreads();
    const float* Xn = X + (long)n * Cin * HW;
    float acc[MT];
    #pragma unroll
    for (int o = 0; o < MT; ++o) acc[o] = 0.f;
    #pragma unroll 4
    for (int c = 0; c < Cin; ++c) {
        const float v = Xn[(long)c * HW + p];
        #pragma unroll
        for (int o = 0; o < MT; ++o) acc[o] = fmaf(sW[o * 176 + c], v, acc[o]);
    }
    #pragma unroll
    for (int o = 0; o < MT; ++o)
        Out[((long)n * M + m0 + o) * HW + p] = acc[o] + bias[m0 + o];
}

// ---------------- presoftmax: S[n,q,k] = sum_j K[n,j,k]*Q[n,j,q]  (lower tiles only) ----------------
__global__ void qk_kernel(const float* __restrict__ Kt, const float* __restrict__ Qt,
                          float* __restrict__ S) {
    const int n  = blockIdx.z;
    const int q0 = blockIdx.y * 64;
    const int k0 = blockIdx.x * 64;
    if (k0 > q0) return;
    __shared__ float sK[16][64];
    __shared__ float sQ[16][64];
    const float* Kn = Kt + (long)n * KDIM * HW;
    const float* Qn = Qt + (long)n * KDIM * HW;
    const int p  = threadIdx.x & 63;
    const int jr = threadIdx.x >> 6;
    #pragma unroll
    for (int pass = 0; pass < 4; ++pass) {
        const int j = jr + pass * 4;
        sK[j][p] = Kn[(long)j * HW + k0 + p];
        sQ[j][p] = Qn[(long)j * HW + q0 + p];
    }
    __syncthreads();
    const int tx = threadIdx.x & 15, ty = threadIdx.x >> 4;
    float acc[4][4] = {};
    #pragma unroll
    for (int j = 0; j < 16; ++j) {
        const float4 q4 = *reinterpret_cast<const float4*>(&sQ[j][ty * 4]);
        const float4 k4 = *reinterpret_cast<const float4*>(&sK[j][tx * 4]);
        const float qr[4] = {q4.x, q4.y, q4.z, q4.w};
        const float kr[4] = {k4.x, k4.y, k4.z, k4.w};
        #pragma unroll
        for (int i = 0; i < 4; ++i)
            #pragma unroll
            for (int jj = 0; jj < 4; ++jj)
                acc[i][jj] = fmaf(qr[i], kr[jj], acc[i][jj]);
    }
    float* Sn = S + (long)n * HW * HW;
    #pragma unroll
    for (int i = 0; i < 4; ++i) {
        float4 r = {acc[i][0], acc[i][1], acc[i][2], acc[i][3]};
        *reinterpret_cast<float4*>(&Sn[(long)(q0 + ty * 4 + i) * HW + k0 + tx * 4]) = r;
    }
}

// ---------------- causal softmax per row (faithful semantics) ----------------
__global__ void softmax_kernel(float* __restrict__ S) {
    const int q = blockIdx.x;
    const int n = blockIdx.y;
    float* row = S + ((long)n * HW + (long)q) * HW;
    const int tid = threadIdx.x;  // 256
    __shared__ float red[256];

    float vals[4];
    float lmax = 0.f;
    #pragma unroll
    for (int i = 0; i < 4; ++i) {
        const int k = tid + i * 256;
        const float s = (k < q) ? row[k] : 0.f;
        vals[i] = s;
        if (k < q) lmax = fmaxf(lmax, s);
    }
    red[tid] = lmax;
    __syncthreads();
    for (int s2 = 128; s2 > 0; s2 >>= 1) {
        if (tid < s2) red[tid] = fmaxf(red[tid], red[tid + s2]);
        __syncthreads();
    }
    const float m = red[0];
    __syncthreads();

    float e[4];
    float lsum = 0.f;
    #pragma unroll
    for (int i = 0; i < 4; ++i) {
        const int k = tid + i * 256;
        e[i] = (k < q) ? expf(vals[i] - m) : 0.f;
        lsum += e[i];
    }
    red[tid] = lsum;
    __syncthreads();
    for (int s2 = 128; s2 > 0; s2 >>= 1) {
        if (tid < s2) red[tid] += red[tid + s2];
        __syncthreads();
    }
    const float Skept = red[0];
    const float D = Skept + (float)(HW - q) * expf(-m);
    const float inv = 1.f / (Skept + 1e-7f * D);
    const int kmax = (q & ~63) + 64;   // av only consumes k < roundup(q+1, 64)
    #pragma unroll
    for (int i = 0; i < 4; ++i) {
        const int k = tid + i * 256;
        if (k < kmax) row[k] = e[i] * inv;
    }
}

// ---------------- AV: Out[n,v,q] = sum_j Att[n,q,j] * V[n,v,j]  (K causally truncated) ----------------
__global__ void av_kernel(const float* __restrict__ Att, const float* __restrict__ V,
                          float* __restrict__ Out) {
    __shared__ float sV[16][80];
    __shared__ float sW[16][64];
    const int n  = blockIdx.y;
    const int q0 = blockIdx.x * 64;
    const float* An = Att + (long)n * HW * HW;
    const float* Vn = V + (long)n * VDIM * HW;
    const int tx = threadIdx.x & 15, ty = threadIdx.x >> 4;
    float acc[5][4] = {};
    const int jmax = min(HW, q0 + 64);

    for (int j0 = 0; j0 < jmax; j0 += 16) {
        for (int i = threadIdx.x; i < 16 * 80; i += 256) {
            const int v = i >> 4, jj = i & 15;
            sV[jj][v] = Vn[(long)v * HW + j0 + jj];
        }
        for (int i = threadIdx.x; i < 16 * 64; i += 256) {
            const int qq = i >> 4, jj = i & 15;
            sW[jj][qq] = An[(long)(q0 + qq) * HW + j0 + jj];
        }
        __syncthreads();
        #pragma unroll
        for (int jj = 0; jj < 16; ++jj) {
            const float4 w4 = *reinterpret_cast<const float4*>(&sW[jj][tx * 4]);
            const float wv[4] = {w4.x, w4.y, w4.z, w4.w};
            #pragma unroll
            for (int i = 0; i < 5; ++i) {
                const float vv = sV[jj][ty * 5 + i];
                #pragma unroll
                for (int j = 0; j < 4; ++j)
                    acc[i][j] = fmaf(vv, wv[j], acc[i][j]);
            }
        }
        __syncthreads();
    }
    #pragma unroll
    for (int i = 0; i < 5; ++i) {
        float4 r = {acc[i][0], acc[i][1], acc[i][2], acc[i][3]};
        *reinterpret_cast<float4*>(&Out[((long)n * VDIM + ty * 5 + i) * HW + q0 + tx * 4]) = r;
    }
}

// ---------------- launcher ----------------
extern "C" void kernel_launch(void* const* d_in, const int* in_sizes, int n_in,
                              void* d_out, int out_size) {
    (void)in_sizes; (void)n_in; (void)out_size;
    const float* x    = (const float*)d_in[0];
    const float* ul   = (const float*)d_in[1];
    const float* b    = (const float*)d_in[2];
    const float* gkWi = (const float*)d_in[3];
    const float* gkbi = (const float*)d_in[4];
    const float* gkWo = (const float*)d_in[5];
    const float* gkbo = (const float*)d_in[6];
    const float* gqWi = (const float*)d_in[7];
    const float* gqbi = (const float*)d_in[8];
    const float* gqWo = (const float*)d_in[9];
    const float* gqbo = (const float*)d_in[10];
    const float* gvWi = (const float*)d_in[11];
    const float* gvbi = (const float*)d_in[12];
    const float* gvWo = (const float*)d_in[13];
    const float* gvbo = (const float*)d_in[14];
    const float* nkW  = (const float*)d_in[15];
    const float* nkb  = (const float*)d_in[16];
    const float* nqW  = (const float*)d_in[17];
    const float* nqb  = (const float*)d_in[18];
    const float* nvW  = (const float*)d_in[19];
    const float* nvb  = (const float*)d_in[20];
    const float* goWi = (const float*)d_in[21];
    const float* gobi = (const float*)d_in[22];
    const float* goWs = (const float*)d_in[23];
    const float* gobs = (const float*)d_in[24];
    const float* goWo = (const float*)d_in[25];
    const float* gobo = (const float*)d_in[26];
    float* out = (float*)d_out;

    float *p_cat, *p_h, *p_gout, *p_keys, *p_quer, *p_vals, *p_att, *p_attv;
    cudaGetSymbolAddress((void**)&p_cat,  g_cat);
    cudaGetSymbolAddress((void**)&p_h,    g_h);
    cudaGetSymbolAddress((void**)&p_gout, g_gout);
    cudaGetSymbolAddress((void**)&p_keys, g_keys);
    cudaGetSymbolAddress((void**)&p_quer, g_quer);
    cudaGetSymbolAddress((void**)&p_vals, g_vals);
    cudaGetSymbolAddress((void**)&p_att,  g_att);
    cudaGetSymbolAddress((void**)&p_attv, g_attv);

    const long sCat = (long)CKC * HW;
    const long sQ   = (long)CQC * HW;
    const long sO   = (long)COC * HW;
    const long sV   = (long)VDIM * HW;

    {
        const long total = (long)NB * CKC * HW;
        build_cat_kernel<<<(unsigned)((total + 255) / 256), 256>>>(x, ul, b, p_cat);
    }

    dim3 gridG(3, NB * 8);   // 3 out-tiles of 64 (Cout<=169), 8 px-tiles of 128

    // --- GRN-K -> keys ---
    gemm_celu_kernel<<<gridG, 256>>>(p_cat, sCat, CKC, gkWi,
                                     nullptr, 0, 0, nullptr, gkbi, nullptr,
                                     CKC, p_h, sCat);
    grn_final_kernel<<<gridG, 256>>>(p_h, sCat, CKC, gkWo, gkbo, p_cat, sCat, p_gout, sCat);
    proj_kernel<16><<<dim3(4, NB, 1), 256>>>(p_gout, CKC, nkW, nkb, p_keys, KDIM);

    // --- GRN-Q -> queries (ul_b is a channel-offset view of cat) ---
    gemm_celu_kernel<<<gridG, 256>>>(p_cat + 3 * HW, sCat, CQC, gqWi,
                                     nullptr, 0, 0, nullptr, gqbi, nullptr,
                                     CQC, p_h, sQ);
    grn_final_kernel<<<gridG, 256>>>(p_h, sQ, CQC, gqWo, gqbo, p_cat + 3 * HW, sCat, p_gout, sQ);
    proj_kernel<16><<<dim3(4, NB, 1), 256>>>(p_gout, CQC, nqW, nqb, p_quer, KDIM);

    // --- GRN-V -> values ---
    gemm_celu_kernel<<<gridG, 256>>>(p_cat, sCat, CKC, gvWi,
                                     nullptr, 0, 0, nullptr, gvbi, nullptr,
                                     CKC, p_h, sCat);
    grn_final_kernel<<<gridG, 256>>>(p_h, sCat, CKC, gvWo, gvbo, p_cat, sCat, p_gout, sCat);
    proj_kernel<16><<<dim3(4, NB, 5), 256>>>(p_gout, CKC, nvW, nvb, p_vals, VDIM);

    // --- attention ---
    qk_kernel<<<dim3(16, 16, NB), 256>>>(p_keys, p_quer, p_att);
    softmax_kernel<<<dim3(HW, NB), 256>>>(p_att);
    av_kernel<<<dim3(16, NB), 256>>>(p_att, p_vals, p_attv);

    // --- GRN-O (aux = att_v), dual-input fused GEMM -> output ---
    gemm_celu_kernel<<<gridG, 256>>>(ul, sO, COC, goWi,
                                     p_attv, sV, VDIM, goWs, gobi, gobs,
                                     COC, p_h, sO);
    grn_final_kernel<<<gridG, 256>>>(p_h, sO, COC, goWo, gobo, ul, sO, out, sO);
}